// round 6
// baseline (speedup 1.0000x reference)
#include <cuda_runtime.h>
#include <cstdint>

// Problem constants: B=8, S=2048, D=256
static constexpr int Bn = 8;
static constexpr int Sn = 2048;
static constexpr int Dn = 256;
static constexpr int MROWS = Bn * Sn;   // 16384

// k-dim permutation within each 8-col group: q -> ((q&3)<<1)|(q>>2)
// puts cols (k, k+4) adjacent so MMA fragments load with LDS.64.
__host__ __device__ __forceinline__ int pidx(int c) {
    return (c & ~7) | (((c & 3) << 1) | ((c >> 2) & 1));
}

// ---------------- device scratch (no cudaMalloc allowed) ----------------
__device__ __align__(16) float g_P[MROWS * Dn];      // head @ U, tf32-rounded, k-permuted
__device__ __align__(16) float g_headR[MROWS * Dn];  // head, tf32-rounded, k-permuted
__device__ __align__(16) float g_depR[MROWS * Dn];   // dep,  tf32-rounded, k-permuted
__device__ __align__(16) float g_UT[Dn * Dn];        // U^T,  tf32-rounded, k-permuted
__device__ float g_hs[MROWS];
__device__ float g_ds[MROWS];

// round-to-nearest fp32 -> tf32
__device__ __forceinline__ float rnd_tf32(float x) {
    uint32_t r;
    asm("cvt.rna.tf32.f32 %0, %1;" : "=r"(r) : "f"(x));
    return __uint_as_float(r);
}

// ---------------- prep: hs/ds row dots (exact fp32) + rounded k-permuted copies ----------------
__global__ void prep_hsds(const float* __restrict__ head,
                          const float* __restrict__ dep,
                          const float* __restrict__ W) {
    int warp = threadIdx.x >> 5, lane = threadIdx.x & 31;
    int row = blockIdx.x * 8 + warp;          // 0 .. 2*MROWS-1
    bool isHead = row < MROWS;
    int rr = isHead ? row : row - MROWS;
    const float* src = isHead ? head : dep;
    float* dst       = isHead ? g_headR : g_depR;
    const float* wv  = isHead ? W : (W + Dn);
    float p = 0.f;
    #pragma unroll
    for (int i = 0; i < 2; i++) {
        int c = (lane + 32 * i) * 4;
        float4 v = *(const float4*)(src + (size_t)rr * Dn + c);
        float4 wl = *(const float4*)(wv + c);
        p += v.x * wl.x + v.y * wl.y + v.z * wl.z + v.w * wl.w;
        // permuted scatter within the 8-col group
        int g = c & ~7;
        int hi = (c >> 2) & 1;
        float* db = dst + (size_t)rr * Dn + g + hi;
        db[0] = rnd_tf32(v.x);
        db[2] = rnd_tf32(v.y);
        db[4] = rnd_tf32(v.z);
        db[6] = rnd_tf32(v.w);
    }
    #pragma unroll
    for (int o = 16; o; o >>= 1) p += __shfl_down_sync(0xFFFFFFFFu, p, o);
    if (lane == 0) { if (isHead) g_hs[rr] = p; else g_ds[rr] = p; }
}

// ---------------- prep: U transpose + round + permute ----------------
__global__ void prep_UT(const float* __restrict__ U) {
    int d = blockIdx.x, e = threadIdx.x;
    g_UT[e * Dn + pidx(d)] = rnd_tf32(U[d * Dn + e]);
}

// ---------------- tf32 MMA GEMM: CTA tile 128x256, warp tile 64x64 ----------------
static constexpr int BM = 128, BN = 256, BK = 32, TH = 256;
static constexpr int STAGES = 4;
static constexpr int ATILE_F = BM * BK;                  // 4096 floats = 16 KB
static constexpr int BTILE_F = BN * BK;                  // 8192 floats = 32 KB
static constexpr uint32_t STAGE_BYTES = (ATILE_F + BTILE_F) * 4;      // 49152
static constexpr uint32_t SMEM_BYTES = STAGES * STAGE_BYTES;          // 196608

__device__ __forceinline__ uint32_t smem_u32(const void* p) {
    uint32_t a;
    asm("{ .reg .u64 t; cvta.to.shared.u64 t, %1; cvt.u32.u64 %0, t; }"
        : "=r"(a) : "l"(p));
    return a;
}

__device__ __forceinline__ void cpasync16(uint32_t dst, const float* src) {
    size_t g = __cvta_generic_to_global(src);
    asm volatile("cp.async.cg.shared.global [%0], [%1], 16;"
                 :: "r"(dst), "l"(g));
}

__device__ __forceinline__ void mma_tf32(float* c, const uint32_t* a, const uint32_t* b) {
    asm volatile(
        "mma.sync.aligned.m16n8k8.row.col.f32.tf32.tf32.f32 "
        "{%0,%1,%2,%3}, {%4,%5,%6,%7}, {%8,%9}, {%0,%1,%2,%3};"
        : "+f"(c[0]), "+f"(c[1]), "+f"(c[2]), "+f"(c[3])
        : "r"(a[0]), "r"(a[1]), "r"(a[2]), "r"(a[3]),
          "r"(b[0]), "r"(b[1]));
}

// mode 0: A = g_headR, B = g_UT (all 256 rows), C = g_P      grid (128, 1, 1)
// mode 1: A = g_P,     B = g_depR,              C = out      grid (16, 8, 8)
__global__ void __launch_bounds__(TH, 1)
gemm_kernel(int mode, float* __restrict__ out, const float* __restrict__ eb) {
    extern __shared__ float sm[];

    const int tid = threadIdx.x;
    const int w = tid >> 5, lane = tid & 31;
    const int wm = w >> 2;        // 0..1  (M warp: 64 rows)
    const int wn = w & 3;         // 0..3  (N warp: 64 cols)
    const int x = blockIdx.x, y = blockIdx.y, z = blockIdx.z;

    const float *Ag, *Bg;
    size_t aRow0, bRow0;
    if (mode == 0) { Ag = g_headR; Bg = g_UT;   aRow0 = (size_t)x * BM; bRow0 = 0; }
    else           { Ag = g_P;     Bg = g_depR; aRow0 = (size_t)z * Sn + (size_t)x * BM;
                                                 bRow0 = (size_t)z * Sn + (size_t)y * BN; }

    const uint32_t sb = smem_u32(sm);

    // ---- async tile loader: swizzled dst; one commit group per chunk ----
    auto load_chunk = [&](int kt) {
        int stg = kt & (STAGES - 1);
        uint32_t baseA = sb + (uint32_t)stg * STAGE_BYTES;
        uint32_t baseB = baseA + ATILE_F * 4;
        int k0 = kt * BK;
        #pragma unroll
        for (int i = 0; i < 4; i++) {          // A: 128 rows x 8 slots
            int cid = i * 256 + tid;
            int r = cid >> 3, c4 = cid & 7;
            uint32_t soff = (uint32_t)(r * 128 + (((2 * c4) ^ ((r & 3) << 2)) << 3));
            cpasync16(baseA + soff, Ag + (aRow0 + r) * Dn + k0 + c4 * 4);
        }
        #pragma unroll
        for (int i = 0; i < 8; i++) {          // B: 256 rows x 8 slots
            int cid = i * 256 + tid;
            int r = cid >> 3, c4 = cid & 7;
            uint32_t soff = (uint32_t)(r * 128 + (((2 * c4) ^ ((r & 3) << 2)) << 3));
            cpasync16(baseB + soff, Bg + (bRow0 + r) * Dn + k0 + c4 * 4);
        }
        asm volatile("cp.async.commit_group;" ::: "memory");
    };

    float acc[4][8][4];
    #pragma unroll
    for (int i = 0; i < 4; i++)
        #pragma unroll
        for (int j = 0; j < 8; j++)
            #pragma unroll
            for (int t = 0; t < 4; t++) acc[i][j][t] = 0.f;

    load_chunk(0);
    load_chunk(1);
    load_chunk(2);

    const int rA = wm * 64 + (lane >> 2);       // A base row
    const int rB = wn * 64 + (lane >> 2);       // B base row
    const int kq = lane & 3;
    const uint32_t sw = ((uint32_t)((lane >> 2) & 3)) << 2;   // per-thread swizzle

    #pragma unroll 1
    for (int kt = 0; kt < 8; kt++) {
        int rem = 7 - kt;
        if (rem >= 2)      { asm volatile("cp.async.wait_group 2;" ::: "memory"); }
        else if (rem == 1) { asm volatile("cp.async.wait_group 1;" ::: "memory"); }
        else               { asm volatile("cp.async.wait_group 0;" ::: "memory"); }
        __syncthreads();
        if (kt + 3 < 8) load_chunk(kt + 3);

        int stg = kt & (STAGES - 1);
        uint32_t baseA = sb + (uint32_t)stg * STAGE_BYTES;
        uint32_t baseB = baseA + ATILE_F * 4;

        #pragma unroll
        for (int ks = 0; ks < 4; ks++) {
            uint32_t slotOff = (((uint32_t)(ks * 4 + kq)) ^ sw) << 3;
            uint32_t a[4][4];
            #pragma unroll
            for (int i = 0; i < 4; i++) {
                uint32_t ad0 = baseA + (uint32_t)(rA + i * 16) * 128 + slotOff;
                float2 f0, f1;
                asm volatile("ld.shared.v2.f32 {%0,%1}, [%2];"
                             : "=f"(f0.x), "=f"(f0.y) : "r"(ad0));
                asm volatile("ld.shared.v2.f32 {%0,%1}, [%2];"
                             : "=f"(f1.x), "=f"(f1.y) : "r"(ad0 + 8 * 128));
                a[i][0] = __float_as_uint(f0.x);
                a[i][2] = __float_as_uint(f0.y);
                a[i][1] = __float_as_uint(f1.x);
                a[i][3] = __float_as_uint(f1.y);
            }
            uint32_t b[8][2];
            #pragma unroll
            for (int j = 0; j < 8; j++) {
                uint32_t bd = baseB + (uint32_t)(rB + j * 8) * 128 + slotOff;
                float2 f;
                asm volatile("ld.shared.v2.f32 {%0,%1}, [%2];"
                             : "=f"(f.x), "=f"(f.y) : "r"(bd));
                b[j][0] = __float_as_uint(f.x);
                b[j][1] = __float_as_uint(f.y);
            }
            #pragma unroll
            for (int i = 0; i < 4; i++)
                #pragma unroll
                for (int j = 0; j < 8; j++)
                    mma_tf32(acc[i][j], a[i], b[j]);
        }
    }

    // ---- epilogue ----
    if (mode == 0) {
        #pragma unroll
        for (int i = 0; i < 4; i++) {
            size_t gr = (aRow0 + wm * 64 + i * 16 + (lane >> 2)) * (size_t)Dn;
            #pragma unroll
            for (int j = 0; j < 8; j++) {
                int c = wn * 64 + j * 8 + (lane & 3) * 2;   // even
                int p0 = pidx(c), p1 = pidx(c + 1);
                g_P[gr + p0]          = rnd_tf32(acc[i][j][0]);
                g_P[gr + p1]          = rnd_tf32(acc[i][j][1]);
                g_P[gr + 8 * Dn + p0] = rnd_tf32(acc[i][j][2]);
                g_P[gr + 8 * Dn + p1] = rnd_tf32(acc[i][j][3]);
            }
        }
    } else {
        float bias = __ldg(eb);
        #pragma unroll
        for (int i = 0; i < 4; i++) {
            int rloc = x * BM + wm * 64 + i * 16 + (lane >> 2);       // row in batch
            size_t hrow = (size_t)z * Sn + rloc;
            float hs0 = g_hs[hrow];
            float hs1 = g_hs[hrow + 8];
            size_t gr0 = ((size_t)z * Sn + rloc) * (size_t)Sn + (size_t)y * BN;
            #pragma unroll
            for (int j = 0; j < 8; j++) {
                int c = wn * 64 + j * 8 + (lane & 3) * 2;
                size_t dcol = (size_t)z * Sn + y * BN + c;
                float d0 = g_ds[dcol], d1 = g_ds[dcol + 1];
                *(float2*)(out + gr0 + c) =
                    make_float2(acc[i][j][0] + hs0 + d0 + bias,
                                acc[i][j][1] + hs0 + d1 + bias);
                *(float2*)(out + gr0 + 8 * (size_t)Sn + c) =
                    make_float2(acc[i][j][2] + hs1 + d0 + bias,
                                acc[i][j][3] + hs1 + d1 + bias);
            }
        }
    }
}

// ---------------- kernel_launch ----------------
extern "C" void kernel_launch(void* const* d_in, const int* in_sizes, int n_in,
                              void* d_out, int out_size) {
    const float* head = (const float*)d_in[0];
    const float* dep  = (const float*)d_in[1];
    const float* U    = (const float*)d_in[2];
    const float* W    = (const float*)d_in[3];
    const float* eb   = (const float*)d_in[4];
    float* out = (float*)d_out;
    (void)in_sizes; (void)n_in; (void)out_size;

    cudaFuncSetAttribute(gemm_kernel,
                         cudaFuncAttributeMaxDynamicSharedMemorySize, SMEM_BYTES);

    prep_hsds<<<(2 * MROWS) / 8, 256>>>(head, dep, W);
    prep_UT<<<Dn, Dn>>>(U);
    // stage 1: P = head @ U   (N = 256 = whole U^T)
    gemm_kernel<<<dim3(MROWS / BM, 1, 1), TH, SMEM_BYTES>>>(0, out, eb);
    // stage 2: out[b] = P[b] @ dep[b]^T + hs + ds + bias
    gemm_kernel<<<dim3(Sn / BM, Sn / BN, Bn), TH, SMEM_BYTES>>>(1, out, eb);
}

// round 7
// speedup vs baseline: 1.0892x; 1.0892x over previous
#include <cuda_runtime.h>
#include <cstdint>

// Problem constants: B=8, S=2048, D=256
static constexpr int Bn = 8;
static constexpr int Sn = 2048;
static constexpr int Dn = 256;
static constexpr int MROWS = Bn * Sn;   // 16384

// k-dim permutation within each 8-col group: q -> ((q&3)<<1)|(q>>2)
// puts cols (k, k+4) adjacent so MMA fragments load with LDS.64.
__host__ __device__ __forceinline__ int pidx(int c) {
    return (c & ~7) | (((c & 3) << 1) | ((c >> 2) & 1));
}

// ---------------- device scratch (no cudaMalloc allowed) ----------------
__device__ __align__(16) float g_P[MROWS * Dn];      // head @ U, tf32-rounded, k-permuted
__device__ __align__(16) float g_headR[MROWS * Dn];  // head, tf32-rounded, k-permuted
__device__ __align__(16) float g_depR[MROWS * Dn];   // dep,  tf32-rounded, k-permuted
__device__ __align__(16) float g_UT[Dn * Dn];        // U^T,  tf32-rounded, k-permuted
__device__ float g_hs[MROWS];
__device__ float g_ds[MROWS];

// round-to-nearest fp32 -> tf32
__device__ __forceinline__ float rnd_tf32(float x) {
    uint32_t r;
    asm("cvt.rna.tf32.f32 %0, %1;" : "=r"(r) : "f"(x));
    return __uint_as_float(r);
}

// ---------------- prep: hs/ds row dots (exact fp32) + rounded k-permuted copies ----------------
__global__ void prep_hsds(const float* __restrict__ head,
                          const float* __restrict__ dep,
                          const float* __restrict__ W) {
    int warp = threadIdx.x >> 5, lane = threadIdx.x & 31;
    int row = blockIdx.x * 8 + warp;          // 0 .. 2*MROWS-1
    bool isHead = row < MROWS;
    int rr = isHead ? row : row - MROWS;
    const float* src = isHead ? head : dep;
    float* dst       = isHead ? g_headR : g_depR;
    const float* wv  = isHead ? W : (W + Dn);
    float p = 0.f;
    #pragma unroll
    for (int i = 0; i < 2; i++) {
        int c = (lane + 32 * i) * 4;
        float4 v = *(const float4*)(src + (size_t)rr * Dn + c);
        float4 wl = *(const float4*)(wv + c);
        p += v.x * wl.x + v.y * wl.y + v.z * wl.z + v.w * wl.w;
        // permuted scatter within the 8-col group
        int g = c & ~7;
        int hi = (c >> 2) & 1;
        float* db = dst + (size_t)rr * Dn + g + hi;
        db[0] = rnd_tf32(v.x);
        db[2] = rnd_tf32(v.y);
        db[4] = rnd_tf32(v.z);
        db[6] = rnd_tf32(v.w);
    }
    #pragma unroll
    for (int o = 16; o; o >>= 1) p += __shfl_down_sync(0xFFFFFFFFu, p, o);
    if (lane == 0) { if (isHead) g_hs[rr] = p; else g_ds[rr] = p; }
}

// ---------------- prep: U transpose + round + permute ----------------
__global__ void prep_UT(const float* __restrict__ U) {
    int d = blockIdx.x, e = threadIdx.x;
    g_UT[e * Dn + pidx(d)] = rnd_tf32(U[d * Dn + e]);
}

// ---------------- tf32 MMA GEMM: CTA tile 128x128, 4 warps, warp tile 64x64 ----------------
static constexpr int BM = 128, BN = 128, BK = 32, TH = 128;
static constexpr int STAGES = 3;
static constexpr int ATILE_F = BM * BK;                  // 4096 floats = 16 KB
static constexpr int BTILE_F = BN * BK;                  // 4096 floats = 16 KB
static constexpr uint32_t STAGE_BYTES = (ATILE_F + BTILE_F) * 4;      // 32768
static constexpr uint32_t SMEM_BYTES = STAGES * STAGE_BYTES;          // 98304

__device__ __forceinline__ uint32_t smem_u32(const void* p) {
    uint32_t a;
    asm("{ .reg .u64 t; cvta.to.shared.u64 t, %1; cvt.u32.u64 %0, t; }"
        : "=r"(a) : "l"(p));
    return a;
}

__device__ __forceinline__ void cpasync16(uint32_t dst, const float* src) {
    size_t g = __cvta_generic_to_global(src);
    asm volatile("cp.async.cg.shared.global [%0], [%1], 16;"
                 :: "r"(dst), "l"(g));
}

__device__ __forceinline__ void mma_tf32(float* c, const uint32_t* a, const uint32_t* b) {
    asm volatile(
        "mma.sync.aligned.m16n8k8.row.col.f32.tf32.tf32.f32 "
        "{%0,%1,%2,%3}, {%4,%5,%6,%7}, {%8,%9}, {%0,%1,%2,%3};"
        : "+f"(c[0]), "+f"(c[1]), "+f"(c[2]), "+f"(c[3])
        : "r"(a[0]), "r"(a[1]), "r"(a[2]), "r"(a[3]),
          "r"(b[0]), "r"(b[1]));
}

// mode 0: A = g_headR, B = g_UT,   C = g_P      grid (128, 2, 1)
// mode 1: A = g_P,     B = g_depR, C = out      grid (16, 16, 8)
__global__ void __launch_bounds__(TH, 2)
gemm_kernel(int mode, float* __restrict__ out, const float* __restrict__ eb) {
    extern __shared__ float sm[];

    const int tid = threadIdx.x;
    const int w = tid >> 5, lane = tid & 31;
    const int wm = w >> 1;        // 0..1  (M warp: 64 rows)
    const int wn = w & 1;         // 0..1  (N warp: 64 cols)
    const int x = blockIdx.x, y = blockIdx.y, z = blockIdx.z;

    const float *Ag, *Bg;
    size_t aRow0, bRow0;
    if (mode == 0) { Ag = g_headR; Bg = g_UT;   aRow0 = (size_t)x * BM; bRow0 = (size_t)y * BN; }
    else           { Ag = g_P;     Bg = g_depR; aRow0 = (size_t)z * Sn + (size_t)x * BM;
                                                 bRow0 = (size_t)z * Sn + (size_t)y * BN; }

    const uint32_t sb = smem_u32(sm);

    // ---- async tile loader: swizzled dst; one commit group per chunk ----
    auto load_chunk = [&](int kt) {
        int stg = kt % STAGES;
        uint32_t baseA = sb + (uint32_t)stg * STAGE_BYTES;
        uint32_t baseB = baseA + ATILE_F * 4;
        int k0 = kt * BK;
        #pragma unroll
        for (int i = 0; i < 8; i++) {          // A: 128 rows x 8 slots, 128 threads
            int cid = i * 128 + tid;
            int r = cid >> 3, c4 = cid & 7;
            uint32_t soff = (uint32_t)(r * 128 + (((2 * c4) ^ ((r & 3) << 2)) << 3));
            cpasync16(baseA + soff, Ag + (aRow0 + r) * Dn + k0 + c4 * 4);
        }
        #pragma unroll
        for (int i = 0; i < 8; i++) {          // B: 128 rows x 8 slots
            int cid = i * 128 + tid;
            int r = cid >> 3, c4 = cid & 7;
            uint32_t soff = (uint32_t)(r * 128 + (((2 * c4) ^ ((r & 3) << 2)) << 3));
            cpasync16(baseB + soff, Bg + (bRow0 + r) * Dn + k0 + c4 * 4);
        }
        asm volatile("cp.async.commit_group;" ::: "memory");
    };

    float acc[4][8][4];
    #pragma unroll
    for (int i = 0; i < 4; i++)
        #pragma unroll
        for (int j = 0; j < 8; j++)
            #pragma unroll
            for (int t = 0; t < 4; t++) acc[i][j][t] = 0.f;

    load_chunk(0);
    load_chunk(1);

    const int rA = wm * 64 + (lane >> 2);       // A base row
    const int rB = wn * 64 + (lane >> 2);       // B base row
    const int kq = lane & 3;
    const uint32_t sw = ((uint32_t)((lane >> 2) & 3)) << 2;   // per-thread swizzle

    #pragma unroll 1
    for (int kt = 0; kt < 8; kt++) {
        if (kt == 7) { asm volatile("cp.async.wait_group 0;" ::: "memory"); }
        else         { asm volatile("cp.async.wait_group 1;" ::: "memory"); }
        __syncthreads();
        if (kt + 2 < 8) load_chunk(kt + 2);

        int stg = kt % STAGES;
        uint32_t baseA = sb + (uint32_t)stg * STAGE_BYTES;
        uint32_t baseB = baseA + ATILE_F * 4;

        #pragma unroll
        for (int ks = 0; ks < 4; ks++) {
            uint32_t slotOff = (((uint32_t)(ks * 4 + kq)) ^ sw) << 3;
            uint32_t a[4][4];
            #pragma unroll
            for (int i = 0; i < 4; i++) {
                uint32_t ad0 = baseA + (uint32_t)(rA + i * 16) * 128 + slotOff;
                float2 f0, f1;
                asm volatile("ld.shared.v2.f32 {%0,%1}, [%2];"
                             : "=f"(f0.x), "=f"(f0.y) : "r"(ad0));
                asm volatile("ld.shared.v2.f32 {%0,%1}, [%2];"
                             : "=f"(f1.x), "=f"(f1.y) : "r"(ad0 + 8 * 128));
                a[i][0] = __float_as_uint(f0.x);
                a[i][2] = __float_as_uint(f0.y);
                a[i][1] = __float_as_uint(f1.x);
                a[i][3] = __float_as_uint(f1.y);
            }
            uint32_t b[8][2];
            #pragma unroll
            for (int j = 0; j < 8; j++) {
                uint32_t bd = baseB + (uint32_t)(rB + j * 8) * 128 + slotOff;
                float2 f;
                asm volatile("ld.shared.v2.f32 {%0,%1}, [%2];"
                             : "=f"(f.x), "=f"(f.y) : "r"(bd));
                b[j][0] = __float_as_uint(f.x);
                b[j][1] = __float_as_uint(f.y);
            }
            #pragma unroll
            for (int i = 0; i < 4; i++)
                #pragma unroll
                for (int j = 0; j < 8; j++)
                    mma_tf32(acc[i][j], a[i], b[j]);
        }
    }

    // ---- epilogue ----
    if (mode == 0) {
        size_t col0 = (size_t)y * BN;
        #pragma unroll
        for (int i = 0; i < 4; i++) {
            size_t gr = (aRow0 + wm * 64 + i * 16 + (lane >> 2)) * (size_t)Dn + col0;
            #pragma unroll
            for (int j = 0; j < 8; j++) {
                int c = wn * 64 + j * 8 + (lane & 3) * 2;   // even
                int p0 = pidx(c), p1 = pidx(c + 1);
                g_P[gr + p0]          = rnd_tf32(acc[i][j][0]);
                g_P[gr + p1]          = rnd_tf32(acc[i][j][1]);
                g_P[gr + 8 * Dn + p0] = rnd_tf32(acc[i][j][2]);
                g_P[gr + 8 * Dn + p1] = rnd_tf32(acc[i][j][3]);
            }
        }
    } else {
        float bias = __ldg(eb);
        #pragma unroll
        for (int i = 0; i < 4; i++) {
            int rloc = x * BM + wm * 64 + i * 16 + (lane >> 2);       // row in batch
            size_t hrow = (size_t)z * Sn + rloc;
            float hs0 = g_hs[hrow];
            float hs1 = g_hs[hrow + 8];
            size_t gr0 = ((size_t)z * Sn + rloc) * (size_t)Sn + (size_t)y * BN;
            #pragma unroll
            for (int j = 0; j < 8; j++) {
                int c = wn * 64 + j * 8 + (lane & 3) * 2;
                size_t dcol = (size_t)z * Sn + y * BN + c;
                float d0 = g_ds[dcol], d1 = g_ds[dcol + 1];
                *(float2*)(out + gr0 + c) =
                    make_float2(acc[i][j][0] + hs0 + d0 + bias,
                                acc[i][j][1] + hs0 + d1 + bias);
                *(float2*)(out + gr0 + 8 * (size_t)Sn + c) =
                    make_float2(acc[i][j][2] + hs1 + d0 + bias,
                                acc[i][j][3] + hs1 + d1 + bias);
            }
        }
    }
}

// ---------------- kernel_launch ----------------
extern "C" void kernel_launch(void* const* d_in, const int* in_sizes, int n_in,
                              void* d_out, int out_size) {
    const float* head = (const float*)d_in[0];
    const float* dep  = (const float*)d_in[1];
    const float* U    = (const float*)d_in[2];
    const float* W    = (const float*)d_in[3];
    const float* eb   = (const float*)d_in[4];
    float* out = (float*)d_out;
    (void)in_sizes; (void)n_in; (void)out_size;

    cudaFuncSetAttribute(gemm_kernel,
                         cudaFuncAttributeMaxDynamicSharedMemorySize, SMEM_BYTES);

    prep_hsds<<<(2 * MROWS) / 8, 256>>>(head, dep, W);
    prep_UT<<<Dn, Dn>>>(U);
    // stage 1: P = head @ U
    gemm_kernel<<<dim3(MROWS / BM, Dn / BN, 1), TH, SMEM_BYTES>>>(0, out, eb);
    // stage 2: out[b] = P[b] @ dep[b]^T + hs + ds + bias
    gemm_kernel<<<dim3(Sn / BM, Sn / BN, Bn), TH, SMEM_BYTES>>>(1, out, eb);
}